// round 5
// baseline (speedup 1.0000x reference)
#include <cuda_runtime.h>

#define BATCH 64
#define TDIM  2048
#define QDIM  512
#define KDIM  512
#define QSPLIT 4
#define QCHUNK (QDIM / QSPLIT)   // 128

// Scratch (no allocations allowed in kernel_launch)
__device__ float    g_part[QSPLIT][BATCH * KDIM];  // partial mids per q-chunk
__device__ float    g_sums[BATCH];
__device__ unsigned g_count[BATCH];

// ---------------------------------------------------------------------------
// Kernel 1: partial mids. g_part[qs][b,k] = sum_{q in chunk} W[k,q]*query[b,q]
// grid = 2048: qs = x&3, kt = (x>>2)&31, bt = x>>7. 8 warps/block; each warp
// owns ONE k-pair: single L2 W load -> FMA -> one shfl chain. Block 0 zeroes
// g_sums / g_count (re-zeroed every replay, before scores runs).
// ---------------------------------------------------------------------------
__global__ void __launch_bounds__(256)
mids_kernel(const float* __restrict__ query,
            const float* __restrict__ W)
{
    const int qs = blockIdx.x & 3;
    const int kt = (blockIdx.x >> 2) & 31;   // 0..31 (16 k each)
    const int bt = blockIdx.x >> 7;          // 0..15 (4 b each)

    if (blockIdx.x == 0 && threadIdx.x < BATCH) {
        g_sums[threadIdx.x]  = 0.0f;
        g_count[threadIdx.x] = 0u;
    }

    __shared__ float q_s[4][QCHUNK];
    for (int i = threadIdx.x; i < 4 * QCHUNK; i += blockDim.x) {
        int bb = i >> 7;
        int q  = i & (QCHUNK - 1);
        q_s[bb][q] = query[(size_t)(bt * 4 + bb) * QDIM + qs * QCHUNK + q];
    }
    __syncthreads();

    const int warp = threadIdx.x >> 5;
    const int lane = threadIdx.x & 31;

    float4 qv[4];
#pragma unroll
    for (int bb = 0; bb < 4; bb++)
        qv[bb] = reinterpret_cast<const float4*>(q_s[bb])[lane];

    const int k0 = kt * 16 + warp * 2;
    const int k1 = k0 + 1;
    const float4 wa = reinterpret_cast<const float4*>(
        W + (size_t)k0 * QDIM + qs * QCHUNK)[lane];
    const float4 wb = reinterpret_cast<const float4*>(
        W + (size_t)k1 * QDIM + qs * QCHUNK)[lane];

    float a[2][4];
#pragma unroll
    for (int bb = 0; bb < 4; bb++) {
        const float4 v = qv[bb];
        a[0][bb] = wa.x * v.x + wa.y * v.y + wa.z * v.z + wa.w * v.w;
        a[1][bb] = wb.x * v.x + wb.y * v.y + wb.z * v.z + wb.w * v.w;
    }
#pragma unroll
    for (int o = 16; o; o >>= 1) {
#pragma unroll
        for (int bb = 0; bb < 4; bb++) {
            a[0][bb] += __shfl_xor_sync(0xffffffffu, a[0][bb], o);
            a[1][bb] += __shfl_xor_sync(0xffffffffu, a[1][bb], o);
        }
    }
    if (lane == 0) {
#pragma unroll
        for (int bb = 0; bb < 4; bb++) {
            const int b = bt * 4 + bb;
            g_part[qs][(size_t)b * KDIM + k0] = a[0][bb];
            g_part[qs][(size_t)b * KDIM + k1] = a[1][bb];
        }
    }
}

// ---------------------------------------------------------------------------
// Kernel 2: LANE-PER-ROW scores + fused softmax normalization.
// e[b,t] = exp(tanh(key[b,t,:].mids[b,:] + bias)); last block per batch
// rescales in place. tanh in (-1,1) -> exp bounded -> no max pass needed.
//
// Each lane owns one t-row: reads its row as 128 sequential float4s
// (continuous independent LDGs, no burst/drain), mids comes from smem as a
// per-step BROADCAST (all lanes same address -> 1-cycle LDS, zero shfl in
// the hot loop). 4 accumulators break the FMA dependence chain.
// Block = 128 threads (4 warps = 128 rows), grid = 64*16 = 1024 blocks ->
// ~10 resident blocks/SM, single wave.
// ---------------------------------------------------------------------------
__global__ void __launch_bounds__(128)
scores_kernel(const float* __restrict__ key,
              const float* __restrict__ bias,
              float* __restrict__ out)
{
    const int b     = blockIdx.x >> 4;   // 0..63
    const int chunk = blockIdx.x & 15;   // 0..15 (128 rows each)

    __shared__ float ms[KDIM];
    __shared__ float blockSum;
    __shared__ int   isLast;
    __shared__ float invTotal;
    if (threadIdx.x == 0) { blockSum = 0.0f; isLast = 0; }

    // Stage mids (= sum of 4 q-chunk partials): 128 threads x 1 float4
    {
        const int i = threadIdx.x;  // 0..127 float4 indices
        float4 x0 = reinterpret_cast<const float4*>(g_part[0] + (size_t)b * KDIM)[i];
        float4 x1 = reinterpret_cast<const float4*>(g_part[1] + (size_t)b * KDIM)[i];
        float4 x2 = reinterpret_cast<const float4*>(g_part[2] + (size_t)b * KDIM)[i];
        float4 x3 = reinterpret_cast<const float4*>(g_part[3] + (size_t)b * KDIM)[i];
        float4 s;
        s.x = (x0.x + x1.x) + (x2.x + x3.x);
        s.y = (x0.y + x1.y) + (x2.y + x3.y);
        s.z = (x0.z + x1.z) + (x2.z + x3.z);
        s.w = (x0.w + x1.w) + (x2.w + x3.w);
        reinterpret_cast<float4*>(ms)[i] = s;
    }
    __syncthreads();

    const int row = chunk * 128 + threadIdx.x;   // this lane's t index
    const float4* kr = reinterpret_cast<const float4*>(
        key + ((size_t)b * TDIM + row) * KDIM);
    const float4* m4 = reinterpret_cast<const float4*>(ms);

    float acc0 = 0.f, acc1 = 0.f, acc2 = 0.f, acc3 = 0.f;
#pragma unroll
    for (int j = 0; j < KDIM / 4; j += 4) {
        float4 v0 = __ldcs(kr + j + 0);
        float4 v1 = __ldcs(kr + j + 1);
        float4 v2 = __ldcs(kr + j + 2);
        float4 v3 = __ldcs(kr + j + 3);
        float4 m0 = m4[j + 0];   // broadcast LDS (same addr across warp)
        float4 m1 = m4[j + 1];
        float4 m2 = m4[j + 2];
        float4 m3 = m4[j + 3];
        acc0 += v0.x * m0.x + v0.y * m0.y + v0.z * m0.z + v0.w * m0.w;
        acc1 += v1.x * m1.x + v1.y * m1.y + v1.z * m1.z + v1.w * m1.w;
        acc2 += v2.x * m2.x + v2.y * m2.y + v2.z * m2.z + v2.w * m2.w;
        acc3 += v3.x * m3.x + v3.y * m3.y + v3.z * m3.z + v3.w * m3.w;
    }
    const float s = (acc0 + acc1) + (acc2 + acc3);
    const float e = __expf(tanhf(s + bias[0]));

    out[(size_t)b * TDIM + row] = e;   // fully coalesced, 1 float/lane

    // warp-reduce e, one atomic per warp
    float wsum = e;
#pragma unroll
    for (int o = 16; o; o >>= 1)
        wsum += __shfl_xor_sync(0xffffffffu, wsum, o);
    __syncthreads();   // blockSum init visible
    if ((threadIdx.x & 31) == 0) atomicAdd(&blockSum, wsum);
    __syncthreads();   // all stores + blockSum complete (program order)

    if (threadIdx.x == 0) {
        __threadfence();                  // publish this block's out stores
        atomicAdd(&g_sums[b], blockSum);
        __threadfence();                  // publish sum before counter
        unsigned old = atomicAdd(&g_count[b], 1u);
        if (old == 15u) {                 // last block for this batch
            isLast = 1;
            __threadfence();
            invTotal = 1.0f / atomicAdd(&g_sums[b], 0.0f);  // L2-coherent read
        }
    }
    __syncthreads();

    if (isLast) {
        const float inv = invTotal;
        float4* o4 = reinterpret_cast<float4*>(out + (size_t)b * TDIM);
#pragma unroll
        for (int r = 0; r < 4; r++) {
            const int i = threadIdx.x + r * 128;  // 512 float4 per batch
            float4 v = __ldcg(&o4[i]);
            v.x *= inv; v.y *= inv; v.z *= inv; v.w *= inv;
            o4[i] = v;
        }
    }
}

// ---------------------------------------------------------------------------
// Inputs (metadata order): query [64,512], key [64,2048,512], W [512,512],
// bias [1]. Output: [64,2048] float32.
// ---------------------------------------------------------------------------
extern "C" void kernel_launch(void* const* d_in, const int* in_sizes, int n_in,
                              void* d_out, int out_size)
{
    const float* query = (const float*)d_in[0];
    const float* key   = (const float*)d_in[1];
    const float* W     = (const float*)d_in[2];
    const float* bias  = (const float*)d_in[3];
    float* out = (float*)d_out;

    mids_kernel<<<2048, 256>>>(query, W);
    scores_kernel<<<BATCH * 16, 128>>>(key, bias, out);
}

// round 6
// speedup vs baseline: 1.3974x; 1.3974x over previous
#include <cuda_runtime.h>

#define BATCH 64
#define TDIM  2048
#define QDIM  512
#define KDIM  512
#define QSPLIT 4
#define QCHUNK (QDIM / QSPLIT)   // 128

// Scratch (no allocations allowed in kernel_launch)
__device__ float g_part[QSPLIT][BATCH * KDIM];  // partial mids per q-chunk
__device__ float g_sums[BATCH];

// ---------------------------------------------------------------------------
// Kernel 1: partial mids. g_part[qs][b,k] = sum_{q in chunk} W[k,q]*query[b,q]
// grid = 2048: qs = x&3, kt = (x>>2)&31, bt = x>>7. 8 warps/block; each warp
// owns ONE k-pair: single L2 W load -> FMA -> one shfl chain. Block 0 zeroes
// g_sums.
// ---------------------------------------------------------------------------
__global__ void __launch_bounds__(256)
mids_kernel(const float* __restrict__ query,
            const float* __restrict__ W)
{
    const int qs = blockIdx.x & 3;
    const int kt = (blockIdx.x >> 2) & 31;   // 0..31 (16 k each)
    const int bt = blockIdx.x >> 7;          // 0..15 (4 b each)

    if (blockIdx.x == 0 && threadIdx.x < BATCH) g_sums[threadIdx.x] = 0.0f;

    __shared__ float q_s[4][QCHUNK];
    for (int i = threadIdx.x; i < 4 * QCHUNK; i += blockDim.x) {
        int bb = i >> 7;
        int q  = i & (QCHUNK - 1);
        q_s[bb][q] = query[(size_t)(bt * 4 + bb) * QDIM + qs * QCHUNK + q];
    }
    __syncthreads();

    const int warp = threadIdx.x >> 5;
    const int lane = threadIdx.x & 31;

    float4 qv[4];
#pragma unroll
    for (int bb = 0; bb < 4; bb++)
        qv[bb] = reinterpret_cast<const float4*>(q_s[bb])[lane];

    const int k0 = kt * 16 + warp * 2;
    const int k1 = k0 + 1;
    const float4 wa = reinterpret_cast<const float4*>(
        W + (size_t)k0 * QDIM + qs * QCHUNK)[lane];
    const float4 wb = reinterpret_cast<const float4*>(
        W + (size_t)k1 * QDIM + qs * QCHUNK)[lane];

    float a[2][4];
#pragma unroll
    for (int bb = 0; bb < 4; bb++) {
        const float4 v = qv[bb];
        a[0][bb] = wa.x * v.x + wa.y * v.y + wa.z * v.z + wa.w * v.w;
        a[1][bb] = wb.x * v.x + wb.y * v.y + wb.z * v.z + wb.w * v.w;
    }
#pragma unroll
    for (int o = 16; o; o >>= 1) {
#pragma unroll
        for (int bb = 0; bb < 4; bb++) {
            a[0][bb] += __shfl_xor_sync(0xffffffffu, a[0][bb], o);
            a[1][bb] += __shfl_xor_sync(0xffffffffu, a[1][bb], o);
        }
    }
    if (lane == 0) {
#pragma unroll
        for (int bb = 0; bb < 4; bb++) {
            const int b = bt * 4 + bb;
            g_part[qs][(size_t)b * KDIM + k0] = a[0][bb];
            g_part[qs][(size_t)b * KDIM + k1] = a[1][bb];
        }
    }
}

// ---------------------------------------------------------------------------
// Kernel 2: e[b,t] = exp(tanh(key[b,t,:] . mids[b,:] + bias)); accumulate
// per-batch sums. tanh in (-1,1) -> exp bounded -> no max pass needed.
// grid = 64*32 = 2048 blocks (64 rows each), 256 threads = 8 warps.
// Each warp: 8 rows in ONE burst of 32 independent streaming LDG.128
// (warp-coalesced: each LDG touches exactly 4 lines), single base pointer +
// immediate offsets, then one interleaved 8-way shfl-reduce epilogue.
// mids staged through smem once per block, then per-lane registers.
// No fences / no fused norm: the separate norm kernel provides the sync.
// ---------------------------------------------------------------------------
__global__ void __launch_bounds__(256)
scores_kernel(const float* __restrict__ key,
              const float* __restrict__ bias,
              float* __restrict__ out)
{
    const int b     = blockIdx.x >> 5;   // 0..63
    const int chunk = blockIdx.x & 31;   // 0..31 (64 rows each)

    __shared__ float ms[KDIM];
    __shared__ float blockSum;
    if (threadIdx.x == 0) blockSum = 0.0f;

    // Stage mids (= sum of 4 q-chunk partials): threads 0..127, 1 float4 each
    if (threadIdx.x < KDIM / 4) {
        const int i = threadIdx.x;
        float4 x0 = reinterpret_cast<const float4*>(g_part[0] + (size_t)b * KDIM)[i];
        float4 x1 = reinterpret_cast<const float4*>(g_part[1] + (size_t)b * KDIM)[i];
        float4 x2 = reinterpret_cast<const float4*>(g_part[2] + (size_t)b * KDIM)[i];
        float4 x3 = reinterpret_cast<const float4*>(g_part[3] + (size_t)b * KDIM)[i];
        float4 s;
        s.x = (x0.x + x1.x) + (x2.x + x3.x);
        s.y = (x0.y + x1.y) + (x2.y + x3.y);
        s.z = (x0.z + x1.z) + (x2.z + x3.z);
        s.w = (x0.w + x1.w) + (x2.w + x3.w);
        reinterpret_cast<float4*>(ms)[i] = s;
    }
    __syncthreads();

    const int warp = threadIdx.x >> 5;
    const int lane = threadIdx.x & 31;

    float4 m[4];
#pragma unroll
    for (int j = 0; j < 4; j++)
        m[j] = reinterpret_cast<const float4*>(ms)[lane + 32 * j];

    const int ta = chunk * 64 + warp * 8;
    const float4* kb = reinterpret_cast<const float4*>(
        key + ((size_t)b * TDIM + ta) * KDIM);

    float a0 = 0.f, a1 = 0.f, a2 = 0.f, a3 = 0.f;
    float a4 = 0.f, a5 = 0.f, a6 = 0.f, a7 = 0.f;
#pragma unroll
    for (int j = 0; j < 4; j++) {
        const int idx = lane + 32 * j;
        const float4 mv = m[j];
        float4 v0 = __ldcs(kb + idx + 0 * 128);
        float4 v1 = __ldcs(kb + idx + 1 * 128);
        float4 v2 = __ldcs(kb + idx + 2 * 128);
        float4 v3 = __ldcs(kb + idx + 3 * 128);
        float4 v4 = __ldcs(kb + idx + 4 * 128);
        float4 v5 = __ldcs(kb + idx + 5 * 128);
        float4 v6 = __ldcs(kb + idx + 6 * 128);
        float4 v7 = __ldcs(kb + idx + 7 * 128);
        a0 += v0.x * mv.x + v0.y * mv.y + v0.z * mv.z + v0.w * mv.w;
        a1 += v1.x * mv.x + v1.y * mv.y + v1.z * mv.z + v1.w * mv.w;
        a2 += v2.x * mv.x + v2.y * mv.y + v2.z * mv.z + v2.w * mv.w;
        a3 += v3.x * mv.x + v3.y * mv.y + v3.z * mv.z + v3.w * mv.w;
        a4 += v4.x * mv.x + v4.y * mv.y + v4.z * mv.z + v4.w * mv.w;
        a5 += v5.x * mv.x + v5.y * mv.y + v5.z * mv.z + v5.w * mv.w;
        a6 += v6.x * mv.x + v6.y * mv.y + v6.z * mv.z + v6.w * mv.w;
        a7 += v7.x * mv.x + v7.y * mv.y + v7.z * mv.z + v7.w * mv.w;
    }
#pragma unroll
    for (int o = 16; o; o >>= 1) {
        a0 += __shfl_xor_sync(0xffffffffu, a0, o);
        a1 += __shfl_xor_sync(0xffffffffu, a1, o);
        a2 += __shfl_xor_sync(0xffffffffu, a2, o);
        a3 += __shfl_xor_sync(0xffffffffu, a3, o);
        a4 += __shfl_xor_sync(0xffffffffu, a4, o);
        a5 += __shfl_xor_sync(0xffffffffu, a5, o);
        a6 += __shfl_xor_sync(0xffffffffu, a6, o);
        a7 += __shfl_xor_sync(0xffffffffu, a7, o);
    }

    if (lane == 0) {
        const float bv = bias[0];
        float4 e0, e1;
        e0.x = __expf(tanhf(a0 + bv));
        e0.y = __expf(tanhf(a1 + bv));
        e0.z = __expf(tanhf(a2 + bv));
        e0.w = __expf(tanhf(a3 + bv));
        e1.x = __expf(tanhf(a4 + bv));
        e1.y = __expf(tanhf(a5 + bv));
        e1.z = __expf(tanhf(a6 + bv));
        e1.w = __expf(tanhf(a7 + bv));
        float4* op = reinterpret_cast<float4*>(out + (size_t)b * TDIM + ta);
        op[0] = e0;
        op[1] = e1;
        atomicAdd(&blockSum,
                  ((e0.x + e0.y) + (e0.z + e0.w)) +
                  ((e1.x + e1.y) + (e1.z + e1.w)));
    }
    __syncthreads();
    if (threadIdx.x == 0) atomicAdd(&g_sums[b], blockSum);
}

// ---------------------------------------------------------------------------
// Kernel 3: normalize in place. 32768 float4s, b = (float4 index) / 512.
// ---------------------------------------------------------------------------
__global__ void norm_kernel(float* __restrict__ out)
{
    const int i = blockIdx.x * blockDim.x + threadIdx.x; // 0..32767
    const int b = i >> 9;  // 512 float4 per batch row (T=2048)
    const float inv = 1.0f / g_sums[b];
    float4* o4 = reinterpret_cast<float4*>(out);
    float4 v = o4[i];
    v.x *= inv; v.y *= inv; v.z *= inv; v.w *= inv;
    o4[i] = v;
}

// ---------------------------------------------------------------------------
// Inputs (metadata order): query [64,512], key [64,2048,512], W [512,512],
// bias [1]. Output: [64,2048] float32.
// ---------------------------------------------------------------------------
extern "C" void kernel_launch(void* const* d_in, const int* in_sizes, int n_in,
                              void* d_out, int out_size)
{
    const float* query = (const float*)d_in[0];
    const float* key   = (const float*)d_in[1];
    const float* W     = (const float*)d_in[2];
    const float* bias  = (const float*)d_in[3];
    float* out = (float*)d_out;

    mids_kernel<<<2048, 256>>>(query, W);
    scores_kernel<<<BATCH * 32, 256>>>(key, bias, out);
    norm_kernel<<<(BATCH * TDIM / 4) / 256, 256>>>(out);
}